// round 8
// baseline (speedup 1.0000x reference)
#include <cuda_runtime.h>
#include <cuda_bf16.h>
#include <math.h>
#include <stdint.h>

#define S_TOTAL 8192
#define DM      1024
#define NHEAD   16
#define HDIM    64
#define CHUNKL  2048
#define NCHUNK  4

// ---------------- scratch (allocation-free rule: __device__ globals) --------
__device__ float g_q[S_TOTAL * DM];
__device__ float g_k[S_TOTAL * DM];
__device__ float g_v[S_TOTAL * DM];
__device__ float g_attn[S_TOTAL * DM];
__device__ __nv_bfloat16 g_xhi[S_TOTAL * DM];
__device__ __nv_bfloat16 g_xlo[S_TOTAL * DM];
__device__ __nv_bfloat16 g_ahi[S_TOTAL * DM];
__device__ __nv_bfloat16 g_alo[S_TOTAL * DM];
__device__ __nv_bfloat16 g_whi[4 * DM * DM];
__device__ __nv_bfloat16 g_wlo[4 * DM * DM];

// ---------------- warp-mma helpers (plain sm_103-safe PTX) ------------------
__device__ __forceinline__ uint32_t smem_u32(const void* p) {
    uint32_t a;
    asm("{ .reg .u64 t; cvta.to.shared.u64 t, %1; cvt.u32.u64 %0, t; }" : "=r"(a) : "l"(p));
    return a;
}
__device__ __forceinline__ void ldsm_x4(uint32_t* r, uint32_t addr) {
    asm volatile("ldmatrix.sync.aligned.m8n8.x4.shared.b16 {%0,%1,%2,%3}, [%4];"
                 : "=r"(r[0]), "=r"(r[1]), "=r"(r[2]), "=r"(r[3]) : "r"(addr));
}
__device__ __forceinline__ void mma_bf16(float* c, const uint32_t* a, const uint32_t* b) {
    asm volatile("mma.sync.aligned.m16n8k16.row.col.f32.bf16.bf16.f32 "
                 "{%0,%1,%2,%3}, {%4,%5,%6,%7}, {%8,%9}, {%0,%1,%2,%3};"
                 : "+f"(c[0]), "+f"(c[1]), "+f"(c[2]), "+f"(c[3])
                 : "r"(a[0]), "r"(a[1]), "r"(a[2]), "r"(a[3]), "r"(b[0]), "r"(b[1]));
}
__device__ __forceinline__ void cp_async16(uint32_t saddr, const void* gaddr) {
    asm volatile("cp.async.cg.shared.global [%0], [%1], 16;" :: "r"(saddr), "l"(gaddr));
}

// ---------------- fp32 -> bf16 hi/lo split ----------------------------------
__global__ void __launch_bounds__(256) split_hi_lo(const float* __restrict__ src,
                                                   __nv_bfloat16* __restrict__ hi,
                                                   __nv_bfloat16* __restrict__ lo,
                                                   int n4) {
    int i = blockIdx.x * 256 + threadIdx.x;
    if (i >= n4) return;
    float4 v = ((const float4*)src)[i];
    float f[4] = {v.x, v.y, v.z, v.w};
    __align__(8) __nv_bfloat16 h[4], l[4];
#pragma unroll
    for (int j = 0; j < 4; j++) {
        h[j] = __float2bfloat16(f[j]);
        l[j] = __float2bfloat16(f[j] - __bfloat162float(h[j]));
    }
    ((uint2*)hi)[i] = *(uint2*)h;
    ((uint2*)lo)[i] = *(uint2*)l;
}

// ---------------- mma.sync GEMM, cp.async double-buffered -------------------
// C[m,n] = sum_k A[m,k]*B[n,k];  C = AhiBhi + AhiBlo + AloBhi (fp32 accum).
// Block 128(M)x64(N), BK=32. 8 warps as 2(M)x4(N); warp tile 64x16.
// Smem rows padded to 80B: rows 0..7 hit distinct banks for ldmatrix.
#define BM 128
#define BN 64
#define BKC 32
// per-stage layout (bytes): Ahi@0 (10240) Alo@10240 Bhi@20480 (5120) Blo@25600
#define STAGE_BYTES 30720
#define GEMM_SMEM   (2 * STAGE_BYTES)

__device__ __forceinline__ void gemm_prefetch(
    uint32_t stb, const __nv_bfloat16* __restrict__ Ahi,
    const __nv_bfloat16* __restrict__ Alo, const __nv_bfloat16* __restrict__ Bhi,
    const __nv_bfloat16* __restrict__ Blo, int bm, int bn, int kc, int K, int tid) {
    {
        int row = tid >> 1, c16 = (tid & 1) * 32;        // 128 rows x 2x32B
        const size_t ga = (size_t)(bm * BM + row) * K + kc + (c16 >> 1);
        cp_async16(stb + row * 80 + c16,          Ahi + ga);
        cp_async16(stb + row * 80 + c16 + 16,     Ahi + ga + 8);
        cp_async16(stb + 10240 + row * 80 + c16,      Alo + ga);
        cp_async16(stb + 10240 + row * 80 + c16 + 16, Alo + ga + 8);
    }
    {
        int row = tid >> 2, c16 = (tid & 3) * 16;        // 64 rows x 4 chunks
        const size_t gb = (size_t)(bn * BN + row) * K + kc + (c16 >> 1);
        cp_async16(stb + 20480 + row * 80 + c16, Bhi + gb);
        cp_async16(stb + 25600 + row * 80 + c16, Blo + gb);
    }
}

__global__ void __launch_bounds__(256) gemm_mma(
    const __nv_bfloat16* __restrict__ Ahi, const __nv_bfloat16* __restrict__ Alo,
    const __nv_bfloat16* __restrict__ Bhi, const __nv_bfloat16* __restrict__ Blo,
    float* __restrict__ C, int M, int N, int K) {
    extern __shared__ __align__(16) char smem[];
    const uint32_t sbase = smem_u32(smem);

    const int tid  = threadIdx.x;
    const int lane = tid & 31;
    const int warp = tid >> 5;
    const int wm = (warp & 1) * 64;
    const int wn = (warp >> 1) * 16;
    const int bm = blockIdx.x, bn = blockIdx.y;

    const uint32_t arow_off = (uint32_t)(wm + (lane & 15)) * 80 + (lane >> 4) * 16;
    const uint32_t bn_off =
        (uint32_t)(wn + (lane & 7) + ((lane >> 4) << 3)) * 80 + ((lane >> 3) & 1) * 16;

    float c[4][2][4];
#pragma unroll
    for (int i = 0; i < 4; i++)
#pragma unroll
        for (int j = 0; j < 2; j++)
#pragma unroll
            for (int t = 0; t < 4; t++) c[i][j][t] = 0.f;

    const int nk = K / BKC;

    gemm_prefetch(sbase, Ahi, Alo, Bhi, Blo, bm, bn, 0, K, tid);
    asm volatile("cp.async.commit_group;");

    for (int kc = 0; kc < nk; kc++) {
        const int st = kc & 1;
        if (kc + 1 < nk) {
            gemm_prefetch(sbase + (st ^ 1) * STAGE_BYTES, Ahi, Alo, Bhi, Blo,
                          bm, bn, (kc + 1) * BKC, K, tid);
            asm volatile("cp.async.commit_group;");
            asm volatile("cp.async.wait_group 1;");
        } else {
            asm volatile("cp.async.wait_group 0;");
        }
        __syncthreads();

        const uint32_t aHi = sbase + st * STAGE_BYTES + arow_off;
        const uint32_t bHi = sbase + st * STAGE_BYTES + 20480 + bn_off;

#pragma unroll
        for (int ks = 0; ks < 2; ks++) {
            // phase 1: hi*hi and hi*lo (ah live, then dies)
            uint32_t ah[4][4], bh[4], bl[4];
#pragma unroll
            for (int mt = 0; mt < 4; mt++)
                ldsm_x4(ah[mt], aHi + mt * (16 * 80) + ks * 32);
            ldsm_x4(bh, bHi + ks * 32);
            ldsm_x4(bl, bHi + 5120 + ks * 32);
#pragma unroll
            for (int mt = 0; mt < 4; mt++)
#pragma unroll
                for (int nt = 0; nt < 2; nt++) {
                    mma_bf16(c[mt][nt], ah[mt], &bh[nt * 2]);   // hi*hi
                    mma_bf16(c[mt][nt], ah[mt], &bl[nt * 2]);   // hi*lo
                }
            // phase 2: lo*hi (al replaces ah's registers)
            uint32_t al[4][4];
#pragma unroll
            for (int mt = 0; mt < 4; mt++)
                ldsm_x4(al[mt], aHi + 10240 + mt * (16 * 80) + ks * 32);
#pragma unroll
            for (int mt = 0; mt < 4; mt++)
#pragma unroll
                for (int nt = 0; nt < 2; nt++)
                    mma_bf16(c[mt][nt], al[mt], &bh[nt * 2]);   // lo*hi
        }
        __syncthreads();
    }

    const int r0 = bm * BM + wm + (lane >> 2);
    const int c0 = bn * BN + wn + (lane & 3) * 2;
#pragma unroll
    for (int mt = 0; mt < 4; mt++)
#pragma unroll
        for (int nt = 0; nt < 2; nt++) {
            const int row = r0 + mt * 16;
            const int col = c0 + nt * 8;
            *(float2*)&C[(size_t)row * N + col]       = make_float2(c[mt][nt][0], c[mt][nt][1]);
            *(float2*)&C[(size_t)(row + 8) * N + col] = make_float2(c[mt][nt][2], c[mt][nt][3]);
        }
}

// ---------------- chunk-local causal attention (fp32, lane-pair split) ------
// 128 threads: lane pair (t, t^1) shares one query; each handles 32 of 64 dims.
__global__ void __launch_bounds__(128) attn_kernel(const float* __restrict__ q,
                                                   const float* __restrict__ k,
                                                   const float* __restrict__ v,
                                                   float* __restrict__ o) {
    __shared__ float KV[64][64];
    __shared__ float Sc[64][65];

    const int t    = threadIdx.x;
    const int qloc = t >> 1;      // 0..63
    const int half = t & 1;       // 0/1: dims [half*32, half*32+32)
    const int qb = blockIdx.x;
    const int h  = blockIdx.y;
    const int ch = blockIdx.z;

    const int    qi   = qb * 64 + qloc;
    const size_t qrow = (size_t)(ch * CHUNKL + qi) * DM + h * HDIM + half * 32;

    float qreg[32];
#pragma unroll
    for (int d = 0; d < 32; d += 4) {
        float4 x = *(const float4*)(q + qrow + d);
        qreg[d] = x.x; qreg[d + 1] = x.y; qreg[d + 2] = x.z; qreg[d + 3] = x.w;
    }

    float m = -INFINITY, l = 0.f;
    float acc[32];
#pragma unroll
    for (int d = 0; d < 32; d++) acc[d] = 0.f;

    for (int kb = 0; kb <= qb; kb++) {
        const size_t tbase = (size_t)(ch * CHUNKL + kb * 64) * DM + h * HDIM;

        __syncthreads();
#pragma unroll
        for (int i = 0; i < 8; i++) {
            int idx = t + i * 128;
            int j = idx >> 4, d4 = (idx & 15) << 2;
            *(float4*)&KV[j][d4] = *(const float4*)(k + tbase + (size_t)j * DM + d4);
        }
        __syncthreads();

        // pass 1: scores (pair-split dot + shuffle combine)
        float mtile = -INFINITY;
#pragma unroll 4
        for (int j = 0; j < 64; j++) {
            float d0 = 0.f;
#pragma unroll
            for (int d = 0; d < 32; d += 4) {
                float4 kv = *(const float4*)&KV[j][half * 32 + d];
                d0 += qreg[d] * kv.x + qreg[d + 1] * kv.y
                    + qreg[d + 2] * kv.z + qreg[d + 3] * kv.w;
            }
            d0 += __shfl_xor_sync(0xffffffffu, d0, 1);
            const int kidx = kb * 64 + j;
            const float s = (kidx > qi) ? -1e30f : d0 * 0.125f;
            Sc[qloc][j] = s;          // both halves write same value
            mtile = fmaxf(mtile, s);
        }

        const float mnew = fmaxf(m, mtile);
        const float corr = __expf(m - mnew);
        l *= corr;
#pragma unroll
        for (int d = 0; d < 32; d++) acc[d] *= corr;
        m = mnew;

        __syncthreads();
#pragma unroll
        for (int i = 0; i < 8; i++) {
            int idx = t + i * 128;
            int j = idx >> 4, d4 = (idx & 15) << 2;
            *(float4*)&KV[j][d4] = *(const float4*)(v + tbase + (size_t)j * DM + d4);
        }
        __syncthreads();

        // pass 2: probs + V accumulation (32 dims per thread)
#pragma unroll 2
        for (int j = 0; j < 64; j++) {
            const float sv = Sc[qloc][j];
            const float p = (sv > -1e29f) ? __expf(sv - m) : 0.f;
            l += p;
#pragma unroll
            for (int d = 0; d < 32; d += 4) {
                float4 vv = *(const float4*)&KV[j][half * 32 + d];
                acc[d]     += p * vv.x;
                acc[d + 1] += p * vv.y;
                acc[d + 2] += p * vv.z;
                acc[d + 3] += p * vv.w;
            }
        }
    }

    const float inv = 1.f / l;
#pragma unroll
    for (int d = 0; d < 32; d += 4) {
        float4 x;
        x.x = acc[d] * inv;     x.y = acc[d + 1] * inv;
        x.z = acc[d + 2] * inv; x.w = acc[d + 3] * inv;
        *(float4*)(o + qrow + d) = x;
    }
}

// ---------------------------------------------------------------------------
extern "C" void kernel_launch(void* const* d_in, const int* in_sizes, int n_in,
                              void* d_out, int out_size) {
    const float* x  = (const float*)d_in[0];
    const float* Wq = (const float*)d_in[1];
    const float* Wk = (const float*)d_in[2];
    const float* Wv = (const float*)d_in[3];
    const float* Wo = (const float*)d_in[4];
    float* out = (float*)d_out;

    float *q, *k, *v, *a;
    __nv_bfloat16 *xhi, *xlo, *ahi, *alo, *whi, *wlo;
    cudaGetSymbolAddress((void**)&q, g_q);
    cudaGetSymbolAddress((void**)&k, g_k);
    cudaGetSymbolAddress((void**)&v, g_v);
    cudaGetSymbolAddress((void**)&a, g_attn);
    cudaGetSymbolAddress((void**)&xhi, g_xhi);
    cudaGetSymbolAddress((void**)&xlo, g_xlo);
    cudaGetSymbolAddress((void**)&ahi, g_ahi);
    cudaGetSymbolAddress((void**)&alo, g_alo);
    cudaGetSymbolAddress((void**)&whi, g_whi);
    cudaGetSymbolAddress((void**)&wlo, g_wlo);

    cudaFuncSetAttribute(gemm_mma, cudaFuncAttributeMaxDynamicSharedMemorySize, GEMM_SMEM);

    const int nx4 = S_TOTAL * DM / 4;
    const int nw4 = DM * DM / 4;
    const float* Ws[4] = {Wq, Wk, Wv, Wo};

    split_hi_lo<<<(nx4 + 255) / 256, 256>>>(x, xhi, xlo, nx4);
    for (int i = 0; i < 4; i++)
        split_hi_lo<<<(nw4 + 255) / 256, 256>>>(Ws[i], whi + (size_t)i * DM * DM,
                                                wlo + (size_t)i * DM * DM, nw4);

    dim3 gg(S_TOTAL / BM, DM / BN);   // (64, 16)
    gemm_mma<<<gg, 256, GEMM_SMEM>>>(xhi, xlo, whi + 0 * (size_t)DM * DM,
                                     wlo + 0 * (size_t)DM * DM, q, S_TOTAL, DM, DM);
    gemm_mma<<<gg, 256, GEMM_SMEM>>>(xhi, xlo, whi + 1 * (size_t)DM * DM,
                                     wlo + 1 * (size_t)DM * DM, k, S_TOTAL, DM, DM);
    gemm_mma<<<gg, 256, GEMM_SMEM>>>(xhi, xlo, whi + 2 * (size_t)DM * DM,
                                     wlo + 2 * (size_t)DM * DM, v, S_TOTAL, DM, DM);

    attn_kernel<<<dim3(CHUNKL / 64, NHEAD, NCHUNK), 128>>>(q, k, v, a);

    split_hi_lo<<<(nx4 + 255) / 256, 256>>>(a, ahi, alo, nx4);
    gemm_mma<<<gg, 256, GEMM_SMEM>>>(ahi, alo, whi + 3 * (size_t)DM * DM,
                                     wlo + 3 * (size_t)DM * DM, out, S_TOTAL, DM, DM);
}

// round 9
// speedup vs baseline: 1.5905x; 1.5905x over previous
#include <cuda_runtime.h>
#include <cuda_bf16.h>
#include <math.h>
#include <stdint.h>

#define S_TOTAL 8192
#define DM      1024
#define NHEAD   16
#define HDIM    64
#define CHUNKL  2048
#define NCHUNK  4

// ---------------- scratch (allocation-free rule: __device__ globals) --------
__device__ float g_q[S_TOTAL * DM];
__device__ float g_k[S_TOTAL * DM];
__device__ float g_v[S_TOTAL * DM];
__device__ float g_attn[S_TOTAL * DM];
__device__ __nv_bfloat16 g_xhi[S_TOTAL * DM];
__device__ __nv_bfloat16 g_xlo[S_TOTAL * DM];
__device__ __nv_bfloat16 g_ahi[S_TOTAL * DM];
__device__ __nv_bfloat16 g_alo[S_TOTAL * DM];
__device__ __nv_bfloat16 g_whi[4 * DM * DM];
__device__ __nv_bfloat16 g_wlo[4 * DM * DM];

// ---------------- warp-mma helpers (plain sm_103-safe PTX) ------------------
__device__ __forceinline__ uint32_t smem_u32(const void* p) {
    uint32_t a;
    asm("{ .reg .u64 t; cvta.to.shared.u64 t, %1; cvt.u32.u64 %0, t; }" : "=r"(a) : "l"(p));
    return a;
}
__device__ __forceinline__ void ldsm_x4(uint32_t* r, uint32_t addr) {
    asm volatile("ldmatrix.sync.aligned.m8n8.x4.shared.b16 {%0,%1,%2,%3}, [%4];"
                 : "=r"(r[0]), "=r"(r[1]), "=r"(r[2]), "=r"(r[3]) : "r"(addr));
}
__device__ __forceinline__ void mma_bf16(float* c, const uint32_t* a, const uint32_t* b) {
    asm volatile("mma.sync.aligned.m16n8k16.row.col.f32.bf16.bf16.f32 "
                 "{%0,%1,%2,%3}, {%4,%5,%6,%7}, {%8,%9}, {%0,%1,%2,%3};"
                 : "+f"(c[0]), "+f"(c[1]), "+f"(c[2]), "+f"(c[3])
                 : "r"(a[0]), "r"(a[1]), "r"(a[2]), "r"(a[3]), "r"(b[0]), "r"(b[1]));
}

// ---------------- fp32 -> bf16 hi/lo split ----------------------------------
__global__ void __launch_bounds__(256) split_hi_lo(const float* __restrict__ src,
                                                   __nv_bfloat16* __restrict__ hi,
                                                   __nv_bfloat16* __restrict__ lo,
                                                   int n4) {
    int i = blockIdx.x * 256 + threadIdx.x;
    if (i >= n4) return;
    float4 v = ((const float4*)src)[i];
    float f[4] = {v.x, v.y, v.z, v.w};
    __align__(8) __nv_bfloat16 h[4], l[4];
#pragma unroll
    for (int j = 0; j < 4; j++) {
        h[j] = __float2bfloat16(f[j]);
        l[j] = __float2bfloat16(f[j] - __bfloat162float(h[j]));
    }
    ((uint2*)hi)[i] = *(uint2*)h;
    ((uint2*)lo)[i] = *(uint2*)l;
}

// ---------------- mma.sync GEMM (R5 known-good serial version) --------------
// C[m,n] = sum_k A[m,k]*B[n,k];  C = AhiBhi + AhiBlo + AloBhi (fp32 accum).
// Block 128(M)x64(N), BK=32. 8 warps as 2(M)x4(N); warp tile 64x16.
// Smem rows padded to 40 bf16 (80B): rows 0..7 hit distinct banks for ldmatrix.
#define BM 128
#define BN 64
#define BKC 32
#define PAD_ROW 40   /* bf16 elems per smem row (80 bytes) */

__global__ void __launch_bounds__(256) gemm_mma(
    const __nv_bfloat16* __restrict__ Ahi, const __nv_bfloat16* __restrict__ Alo,
    const __nv_bfloat16* __restrict__ Bhi, const __nv_bfloat16* __restrict__ Blo,
    float* __restrict__ C, int M, int N, int K) {

    __shared__ __align__(16) __nv_bfloat16 sA[2][BM * PAD_ROW];  // [hi,lo]
    __shared__ __align__(16) __nv_bfloat16 sB[2][BN * PAD_ROW];

    const int tid  = threadIdx.x;
    const int lane = tid & 31;
    const int warp = tid >> 5;
    const int wm = (warp & 1) * 64;     // warp M offset
    const int wn = (warp >> 1) * 16;    // warp N offset
    const int bm = blockIdx.x, bn = blockIdx.y;

    const uint32_t aBase[2] = {smem_u32(&sA[0][0]), smem_u32(&sA[1][0])};
    const uint32_t bBase[2] = {smem_u32(&sB[0][0]), smem_u32(&sB[1][0])};

    // ldmatrix lane offsets (bytes)
    const uint32_t arow_off = (uint32_t)(wm + (lane & 15)) * 80 + (lane >> 4) * 16;
    const uint32_t bn_off =
        (uint32_t)(wn + (lane & 7) + ((lane >> 4) << 3)) * 80 + ((lane >> 3) & 1) * 16;

    float c[4][2][4];
#pragma unroll
    for (int i = 0; i < 4; i++)
#pragma unroll
        for (int j = 0; j < 2; j++)
#pragma unroll
            for (int t = 0; t < 4; t++) c[i][j][t] = 0.f;

    const __nv_bfloat16* aSrc[2] = {Ahi, Alo};
    const __nv_bfloat16* bSrc[2] = {Bhi, Blo};

    for (int kc = 0; kc < K; kc += BKC) {
        __syncthreads();   // previous tile fully consumed
        // ---- A tiles: 128 rows x 32 bf16 (4 x 16B per row) ----
#pragma unroll
        for (int s = 0; s < 2; s++) {
#pragma unroll
            for (int it = 0; it < 2; it++) {
                int id = tid + it * 256;          // 0..511
                int row = id >> 2, c16 = (id & 3) * 16;
                uint4 v = *(const uint4*)(aSrc[s] + (size_t)(bm * BM + row) * K + kc + (c16 >> 1));
                *(uint4*)((char*)&sA[s][0] + row * 80 + c16) = v;
            }
            // ---- B tile: 64 rows ----
            {
                int row = tid >> 2, c16 = (tid & 3) * 16;
                uint4 v = *(const uint4*)(bSrc[s] + (size_t)(bn * BN + row) * K + kc + (c16 >> 1));
                *(uint4*)((char*)&sB[s][0] + row * 80 + c16) = v;
            }
        }
        __syncthreads();

#pragma unroll
        for (int ks = 0; ks < 2; ks++) {           // two k16 steps per chunk
            uint32_t ah[4][4], al[4][4], bh[4], bl[4];
#pragma unroll
            for (int mt = 0; mt < 4; mt++)
                ldsm_x4(ah[mt], aBase[0] + arow_off + mt * (16 * 80) + ks * 32);
            ldsm_x4(bh, bBase[0] + bn_off + ks * 32);
#pragma unroll
            for (int mt = 0; mt < 4; mt++)
                ldsm_x4(al[mt], aBase[1] + arow_off + mt * (16 * 80) + ks * 32);
            ldsm_x4(bl, bBase[1] + bn_off + ks * 32);

#pragma unroll
            for (int mt = 0; mt < 4; mt++)
#pragma unroll
                for (int nt = 0; nt < 2; nt++) {
                    mma_bf16(c[mt][nt], ah[mt], &bh[nt * 2]);   // hi*hi
                    mma_bf16(c[mt][nt], ah[mt], &bl[nt * 2]);   // hi*lo
                    mma_bf16(c[mt][nt], al[mt], &bh[nt * 2]);   // lo*hi
                }
        }
    }

    // ---- epilogue ----
    const int r0 = bm * BM + wm + (lane >> 2);
    const int c0 = bn * BN + wn + (lane & 3) * 2;
#pragma unroll
    for (int mt = 0; mt < 4; mt++)
#pragma unroll
        for (int nt = 0; nt < 2; nt++) {
            const int row = r0 + mt * 16;
            const int col = c0 + nt * 8;
            *(float2*)&C[(size_t)row * N + col]       = make_float2(c[mt][nt][0], c[mt][nt][1]);
            *(float2*)&C[(size_t)(row + 8) * N + col] = make_float2(c[mt][nt][2], c[mt][nt][3]);
        }
}

// ---------------- chunk-local causal attention (fp32, lane-pair split) ------
// 128 threads: lane pair (t, t^1) shares one query; each handles 32 of 64 dims.
__global__ void __launch_bounds__(128) attn_kernel(const float* __restrict__ q,
                                                   const float* __restrict__ k,
                                                   const float* __restrict__ v,
                                                   float* __restrict__ o) {
    __shared__ float KV[64][64];
    __shared__ float Sc[64][65];

    const int t    = threadIdx.x;
    const int qloc = t >> 1;      // 0..63
    const int half = t & 1;       // 0/1: dims [half*32, half*32+32)
    const int qb = blockIdx.x;
    const int h  = blockIdx.y;
    const int ch = blockIdx.z;

    const int    qi   = qb * 64 + qloc;
    const size_t qrow = (size_t)(ch * CHUNKL + qi) * DM + h * HDIM + half * 32;

    float qreg[32];
#pragma unroll
    for (int d = 0; d < 32; d += 4) {
        float4 x = *(const float4*)(q + qrow + d);
        qreg[d] = x.x; qreg[d + 1] = x.y; qreg[d + 2] = x.z; qreg[d + 3] = x.w;
    }

    float m = -INFINITY, l = 0.f;
    float acc[32];
#pragma unroll
    for (int d = 0; d < 32; d++) acc[d] = 0.f;

    for (int kb = 0; kb <= qb; kb++) {
        const size_t tbase = (size_t)(ch * CHUNKL + kb * 64) * DM + h * HDIM;

        __syncthreads();
#pragma unroll
        for (int i = 0; i < 8; i++) {
            int idx = t + i * 128;
            int j = idx >> 4, d4 = (idx & 15) << 2;
            *(float4*)&KV[j][d4] = *(const float4*)(k + tbase + (size_t)j * DM + d4);
        }
        __syncthreads();

        // pass 1: scores (pair-split dot + shuffle combine)
        float mtile = -INFINITY;
#pragma unroll 4
        for (int j = 0; j < 64; j++) {
            float d0 = 0.f;
#pragma unroll
            for (int d = 0; d < 32; d += 4) {
                float4 kv = *(const float4*)&KV[j][half * 32 + d];
                d0 += qreg[d] * kv.x + qreg[d + 1] * kv.y
                    + qreg[d + 2] * kv.z + qreg[d + 3] * kv.w;
            }
            d0 += __shfl_xor_sync(0xffffffffu, d0, 1);
            const int kidx = kb * 64 + j;
            const float s = (kidx > qi) ? -1e30f : d0 * 0.125f;
            Sc[qloc][j] = s;          // both halves write same value
            mtile = fmaxf(mtile, s);
        }

        const float mnew = fmaxf(m, mtile);
        const float corr = __expf(m - mnew);
        l *= corr;
#pragma unroll
        for (int d = 0; d < 32; d++) acc[d] *= corr;
        m = mnew;

        __syncthreads();
#pragma unroll
        for (int i = 0; i < 8; i++) {
            int idx = t + i * 128;
            int j = idx >> 4, d4 = (idx & 15) << 2;
            *(float4*)&KV[j][d4] = *(const float4*)(v + tbase + (size_t)j * DM + d4);
        }
        __syncthreads();

        // pass 2: probs + V accumulation (32 dims per thread)
#pragma unroll 2
        for (int j = 0; j < 64; j++) {
            const float sv = Sc[qloc][j];
            const float p = (sv > -1e29f) ? __expf(sv - m) : 0.f;
            l += p;
#pragma unroll
            for (int d = 0; d < 32; d += 4) {
                float4 vv = *(const float4*)&KV[j][half * 32 + d];
                acc[d]     += p * vv.x;
                acc[d + 1] += p * vv.y;
                acc[d + 2] += p * vv.z;
                acc[d + 3] += p * vv.w;
            }
        }
    }

    const float inv = 1.f / l;
#pragma unroll
    for (int d = 0; d < 32; d += 4) {
        float4 x;
        x.x = acc[d] * inv;     x.y = acc[d + 1] * inv;
        x.z = acc[d + 2] * inv; x.w = acc[d + 3] * inv;
        *(float4*)(o + qrow + d) = x;
    }
}

// ---------------------------------------------------------------------------
extern "C" void kernel_launch(void* const* d_in, const int* in_sizes, int n_in,
                              void* d_out, int out_size) {
    const float* x  = (const float*)d_in[0];
    const float* Wq = (const float*)d_in[1];
    const float* Wk = (const float*)d_in[2];
    const float* Wv = (const float*)d_in[3];
    const float* Wo = (const float*)d_in[4];
    float* out = (float*)d_out;

    float *q, *k, *v, *a;
    __nv_bfloat16 *xhi, *xlo, *ahi, *alo, *whi, *wlo;
    cudaGetSymbolAddress((void**)&q, g_q);
    cudaGetSymbolAddress((void**)&k, g_k);
    cudaGetSymbolAddress((void**)&v, g_v);
    cudaGetSymbolAddress((void**)&a, g_attn);
    cudaGetSymbolAddress((void**)&xhi, g_xhi);
    cudaGetSymbolAddress((void**)&xlo, g_xlo);
    cudaGetSymbolAddress((void**)&ahi, g_ahi);
    cudaGetSymbolAddress((void**)&alo, g_alo);
    cudaGetSymbolAddress((void**)&whi, g_whi);
    cudaGetSymbolAddress((void**)&wlo, g_wlo);

    const int nx4 = S_TOTAL * DM / 4;
    const int nw4 = DM * DM / 4;
    const float* Ws[4] = {Wq, Wk, Wv, Wo};

    split_hi_lo<<<(nx4 + 255) / 256, 256>>>(x, xhi, xlo, nx4);
    for (int i = 0; i < 4; i++)
        split_hi_lo<<<(nw4 + 255) / 256, 256>>>(Ws[i], whi + (size_t)i * DM * DM,
                                                wlo + (size_t)i * DM * DM, nw4);

    dim3 gg(S_TOTAL / BM, DM / BN);   // (64, 16)
    gemm_mma<<<gg, 256>>>(xhi, xlo, whi + 0 * (size_t)DM * DM,
                          wlo + 0 * (size_t)DM * DM, q, S_TOTAL, DM, DM);
    gemm_mma<<<gg, 256>>>(xhi, xlo, whi + 1 * (size_t)DM * DM,
                          wlo + 1 * (size_t)DM * DM, k, S_TOTAL, DM, DM);
    gemm_mma<<<gg, 256>>>(xhi, xlo, whi + 2 * (size_t)DM * DM,
                          wlo + 2 * (size_t)DM * DM, v, S_TOTAL, DM, DM);

    attn_kernel<<<dim3(CHUNKL / 64, NHEAD, NCHUNK), 128>>>(q, k, v, a);

    split_hi_lo<<<(nx4 + 255) / 256, 256>>>(a, ahi, alo, nx4);
    gemm_mma<<<gg, 256>>>(ahi, alo, whi + 3 * (size_t)DM * DM,
                          wlo + 3 * (size_t)DM * DM, out, S_TOTAL, DM, DM);
}

// round 12
// speedup vs baseline: 2.2610x; 1.4216x over previous
#include <cuda_runtime.h>
#include <cuda_bf16.h>
#include <math.h>
#include <stdint.h>

#define S_TOTAL 8192
#define DM      1024
#define NHEAD   16
#define HDIM    64
#define CHUNKL  2048
#define NCHUNK  4

// ---------------- scratch (allocation-free rule: __device__ globals) --------
__device__ float g_q[S_TOTAL * DM];
__device__ float g_k[S_TOTAL * DM];
__device__ float g_v[S_TOTAL * DM];
__device__ float g_attn[S_TOTAL * DM];
__device__ __nv_bfloat16 g_xhi[S_TOTAL * DM];
__device__ __nv_bfloat16 g_xlo[S_TOTAL * DM];
__device__ __nv_bfloat16 g_ahi[S_TOTAL * DM];
__device__ __nv_bfloat16 g_alo[S_TOTAL * DM];
__device__ __nv_bfloat16 g_whi[4 * DM * DM];
__device__ __nv_bfloat16 g_wlo[4 * DM * DM];

// ---------------- warp-mma helpers (plain sm_103-safe PTX) ------------------
__device__ __forceinline__ uint32_t smem_u32(const void* p) {
    uint32_t a;
    asm("{ .reg .u64 t; cvta.to.shared.u64 t, %1; cvt.u32.u64 %0, t; }" : "=r"(a) : "l"(p));
    return a;
}
__device__ __forceinline__ void ldsm_x4(uint32_t* r, uint32_t addr) {
    asm volatile("ldmatrix.sync.aligned.m8n8.x4.shared.b16 {%0,%1,%2,%3}, [%4];"
                 : "=r"(r[0]), "=r"(r[1]), "=r"(r[2]), "=r"(r[3]) : "r"(addr));
}
__device__ __forceinline__ void mma_bf16(float* c, const uint32_t* a, const uint32_t* b) {
    asm volatile("mma.sync.aligned.m16n8k16.row.col.f32.bf16.bf16.f32 "
                 "{%0,%1,%2,%3}, {%4,%5,%6,%7}, {%8,%9}, {%0,%1,%2,%3};"
                 : "+f"(c[0]), "+f"(c[1]), "+f"(c[2]), "+f"(c[3])
                 : "r"(a[0]), "r"(a[1]), "r"(a[2]), "r"(a[3]), "r"(b[0]), "r"(b[1]));
}
__device__ __forceinline__ void cp_async16(uint32_t saddr, const void* gaddr) {
    asm volatile("cp.async.cg.shared.global [%0], [%1], 16;" :: "r"(saddr), "l"(gaddr));
}

// ---------------- fp32 -> bf16 hi/lo split ----------------------------------
__global__ void __launch_bounds__(256) split_hi_lo(const float* __restrict__ src,
                                                   __nv_bfloat16* __restrict__ hi,
                                                   __nv_bfloat16* __restrict__ lo,
                                                   int n4) {
    int i = blockIdx.x * 256 + threadIdx.x;
    if (i >= n4) return;
    float4 v = ((const float4*)src)[i];
    float f[4] = {v.x, v.y, v.z, v.w};
    __align__(8) __nv_bfloat16 h[4], l[4];
#pragma unroll
    for (int j = 0; j < 4; j++) {
        h[j] = __float2bfloat16(f[j]);
        l[j] = __float2bfloat16(f[j] - __bfloat162float(h[j]));
    }
    ((uint2*)hi)[i] = *(uint2*)h;
    ((uint2*)lo)[i] = *(uint2*)l;
}

// ---------------- mma.sync GEMM, cp.async double-buffered (R7 version) ------
// C[m,n] = sum_k A[m,k]*B[n,k];  C = AhiBhi + AhiBlo + AloBhi (fp32 accum).
// Block 128(M)x64(N), BK=32. 8 warps as 2(M)x4(N); warp tile 64x16.
// Smem rows padded to 80B: rows 0..7 hit distinct banks for ldmatrix.
#define BM 128
#define BN 64
#define BKC 32
// per-stage layout (bytes): Ahi@0 (10240) Alo@10240 Bhi@20480 (5120) Blo@25600
#define STAGE_BYTES 30720
#define GEMM_SMEM   (2 * STAGE_BYTES)

__device__ __forceinline__ void gemm_prefetch(
    uint32_t stb, const __nv_bfloat16* const* aS, const __nv_bfloat16* const* bS,
    int bm, int bn, int kc, int K, int tid) {
#pragma unroll
    for (int s = 0; s < 2; s++) {
#pragma unroll
        for (int it = 0; it < 2; it++) {
            int id = tid + it * 256;                 // 0..511
            int row = id >> 2, c16 = (id & 3) * 16;  // 128 rows x 4 chunks
            cp_async16(stb + s * 10240 + row * 80 + c16,
                       aS[s] + (size_t)(bm * BM + row) * K + kc + (c16 >> 1));
        }
        {
            int row = tid >> 2, c16 = (tid & 3) * 16; // 64 rows x 4 chunks
            cp_async16(stb + 20480 + s * 5120 + row * 80 + c16,
                       bS[s] + (size_t)(bn * BN + row) * K + kc + (c16 >> 1));
        }
    }
}

__global__ void __launch_bounds__(256, 2) gemm_mma(
    const __nv_bfloat16* __restrict__ Ahi, const __nv_bfloat16* __restrict__ Alo,
    const __nv_bfloat16* __restrict__ Bhi, const __nv_bfloat16* __restrict__ Blo,
    float* __restrict__ C, int M, int N, int K) {
    extern __shared__ __align__(16) char smem[];
    const uint32_t sbase = smem_u32(smem);

    const int tid  = threadIdx.x;
    const int lane = tid & 31;
    const int warp = tid >> 5;
    const int wm = (warp & 1) * 64;
    const int wn = (warp >> 1) * 16;
    const int bm = blockIdx.x, bn = blockIdx.y;

    const uint32_t arow_off = (uint32_t)(wm + (lane & 15)) * 80 + (lane >> 4) * 16;
    const uint32_t bn_off =
        (uint32_t)(wn + (lane & 7) + ((lane >> 4) << 3)) * 80 + ((lane >> 3) & 1) * 16;

    const __nv_bfloat16* aS[2] = {Ahi, Alo};
    const __nv_bfloat16* bS[2] = {Bhi, Blo};

    float c[4][2][4];
#pragma unroll
    for (int i = 0; i < 4; i++)
#pragma unroll
        for (int j = 0; j < 2; j++)
#pragma unroll
            for (int t = 0; t < 4; t++) c[i][j][t] = 0.f;

    const int nk = K / BKC;

    gemm_prefetch(sbase, aS, bS, bm, bn, 0, K, tid);
    asm volatile("cp.async.commit_group;");

    for (int kc = 0; kc < nk; kc++) {
        const int st = kc & 1;
        if (kc + 1 < nk) {
            gemm_prefetch(sbase + (st ^ 1) * STAGE_BYTES, aS, bS, bm, bn,
                          (kc + 1) * BKC, K, tid);
            asm volatile("cp.async.commit_group;");
            asm volatile("cp.async.wait_group 1;");
        } else {
            asm volatile("cp.async.wait_group 0;");
        }
        __syncthreads();

        const uint32_t aHi = sbase + st * STAGE_BYTES + arow_off;
        const uint32_t bHi = sbase + st * STAGE_BYTES + 20480 + bn_off;

#pragma unroll
        for (int ks = 0; ks < 2; ks++) {
            uint32_t ah[4][4], al[4][4], bh[4], bl[4];
#pragma unroll
            for (int mt = 0; mt < 4; mt++)
                ldsm_x4(ah[mt], aHi + mt * (16 * 80) + ks * 32);
            ldsm_x4(bh, bHi + ks * 32);
#pragma unroll
            for (int mt = 0; mt < 4; mt++)
                ldsm_x4(al[mt], aHi + 10240 + mt * (16 * 80) + ks * 32);
            ldsm_x4(bl, bHi + 5120 + ks * 32);

#pragma unroll
            for (int mt = 0; mt < 4; mt++)
#pragma unroll
                for (int nt = 0; nt < 2; nt++) {
                    mma_bf16(c[mt][nt], ah[mt], &bh[nt * 2]);   // hi*hi
                    mma_bf16(c[mt][nt], ah[mt], &bl[nt * 2]);   // hi*lo
                    mma_bf16(c[mt][nt], al[mt], &bh[nt * 2]);   // lo*hi
                }
        }
        __syncthreads();
    }

    const int r0 = bm * BM + wm + (lane >> 2);
    const int c0 = bn * BN + wn + (lane & 3) * 2;
#pragma unroll
    for (int mt = 0; mt < 4; mt++)
#pragma unroll
        for (int nt = 0; nt < 2; nt++) {
            const int row = r0 + mt * 16;
            const int col = c0 + nt * 8;
            *(float2*)&C[(size_t)row * N + col]       = make_float2(c[mt][nt][0], c[mt][nt][1]);
            *(float2*)&C[(size_t)(row + 8) * N + col] = make_float2(c[mt][nt][2], c[mt][nt][3]);
        }
}

// ---------------- chunk-local causal attention (R5 known-good, 64 thr) ------
__global__ void __launch_bounds__(64) attn_kernel(const float* __restrict__ q,
                                                  const float* __restrict__ k,
                                                  const float* __restrict__ v,
                                                  float* __restrict__ o) {
    __shared__ float KV[64][64];
    __shared__ float Sc[64][65];

    const int t  = threadIdx.x;
    const int qb = blockIdx.x;
    const int h  = blockIdx.y;
    const int ch = blockIdx.z;

    const int    qi   = qb * 64 + t;
    const size_t qrow = (size_t)(ch * CHUNKL + qi) * DM + h * HDIM;

    float qreg[64];
#pragma unroll
    for (int d = 0; d < 64; d += 4) {
        float4 x = *(const float4*)(q + qrow + d);
        qreg[d] = x.x; qreg[d + 1] = x.y; qreg[d + 2] = x.z; qreg[d + 3] = x.w;
    }

    float m = -INFINITY, l = 0.f;
    float acc[64];
#pragma unroll
    for (int d = 0; d < 64; d++) acc[d] = 0.f;

    for (int kb = 0; kb <= qb; kb++) {
        const size_t tbase = (size_t)(ch * CHUNKL + kb * 64) * DM + h * HDIM;

        __syncthreads();
#pragma unroll
        for (int i = 0; i < 16; i++) {
            int idx = t + i * 64;
            int j = idx >> 4, d4 = (idx & 15) << 2;
            *(float4*)&KV[j][d4] = *(const float4*)(k + tbase + (size_t)j * DM + d4);
        }
        __syncthreads();

        float mtile = -INFINITY;
#pragma unroll 4
        for (int j = 0; j < 64; j++) {
            const int kidx = kb * 64 + j;
            float s;
            if (kidx > qi) {
                s = -1e30f;
            } else {
                float d0 = 0.f;
#pragma unroll
                for (int d = 0; d < 64; d += 4) {
                    float4 kv = *(const float4*)&KV[j][d];
                    d0 += qreg[d] * kv.x + qreg[d + 1] * kv.y
                        + qreg[d + 2] * kv.z + qreg[d + 3] * kv.w;
                }
                s = d0 * 0.125f;
            }
            Sc[t][j] = s;
            mtile = fmaxf(mtile, s);
        }

        const float mnew = fmaxf(m, mtile);
        const float corr = __expf(m - mnew);
        l *= corr;
#pragma unroll
        for (int d = 0; d < 64; d++) acc[d] *= corr;
        m = mnew;

        __syncthreads();
#pragma unroll
        for (int i = 0; i < 16; i++) {
            int idx = t + i * 64;
            int j = idx >> 4, d4 = (idx & 15) << 2;
            *(float4*)&KV[j][d4] = *(const float4*)(v + tbase + (size_t)j * DM + d4);
        }
        __syncthreads();

#pragma unroll 2
        for (int j = 0; j < 64; j++) {
            const float sv = Sc[t][j];
            const float p = (sv > -1e29f) ? __expf(sv - m) : 0.f;
            l += p;
#pragma unroll
            for (int d = 0; d < 64; d += 4) {
                float4 vv = *(const float4*)&KV[j][d];
                acc[d]     += p * vv.x;
                acc[d + 1] += p * vv.y;
                acc[d + 2] += p * vv.z;
                acc[d + 3] += p * vv.w;
            }
        }
    }

    const float inv = 1.f / l;
#pragma unroll
    for (int d = 0; d < 64; d += 4) {
        float4 x;
        x.x = acc[d] * inv;     x.y = acc[d + 1] * inv;
        x.z = acc[d + 2] * inv; x.w = acc[d + 3] * inv;
        *(float4*)(o + qrow + d) = x;
    }
}

// ---------------------------------------------------------------------------
extern "C" void kernel_launch(void* const* d_in, const int* in_sizes, int n_in,
                              void* d_out, int out_size) {
    const float* x  = (const float*)d_in[0];
    const float* Wq = (const float*)d_in[1];
    const float* Wk = (const float*)d_in[2];
    const float* Wv = (const float*)d_in[3];
    const float* Wo = (const float*)d_in[4];
    float* out = (float*)d_out;

    float *q, *k, *v, *a;
    __nv_bfloat16 *xhi, *xlo, *ahi, *alo, *whi, *wlo;
    cudaGetSymbolAddress((void**)&q, g_q);
    cudaGetSymbolAddress((void**)&k, g_k);
    cudaGetSymbolAddress((void**)&v, g_v);
    cudaGetSymbolAddress((void**)&a, g_attn);
    cudaGetSymbolAddress((void**)&xhi, g_xhi);
    cudaGetSymbolAddress((void**)&xlo, g_xlo);
    cudaGetSymbolAddress((void**)&ahi, g_ahi);
    cudaGetSymbolAddress((void**)&alo, g_alo);
    cudaGetSymbolAddress((void**)&whi, g_whi);
    cudaGetSymbolAddress((void**)&wlo, g_wlo);

    cudaFuncSetAttribute(gemm_mma, cudaFuncAttributeMaxDynamicSharedMemorySize, GEMM_SMEM);

    const int nx4 = S_TOTAL * DM / 4;
    const int nw4 = DM * DM / 4;
    const float* Ws[4] = {Wq, Wk, Wv, Wo};

    split_hi_lo<<<(nx4 + 255) / 256, 256>>>(x, xhi, xlo, nx4);
    for (int i = 0; i < 4; i++)
        split_hi_lo<<<(nw4 + 255) / 256, 256>>>(Ws[i], whi + (size_t)i * DM * DM,
                                                wlo + (size_t)i * DM * DM, nw4);

    dim3 gg(S_TOTAL / BM, DM / BN);   // (64, 16)
    gemm_mma<<<gg, 256, GEMM_SMEM>>>(xhi, xlo, whi + 0 * (size_t)DM * DM,
                                     wlo + 0 * (size_t)DM * DM, q, S_TOTAL, DM, DM);
    gemm_mma<<<gg, 256, GEMM_SMEM>>>(xhi, xlo, whi + 1 * (size_t)DM * DM,
                                     wlo + 1 * (size_t)DM * DM, k, S_TOTAL, DM, DM);
    gemm_mma<<<gg, 256, GEMM_SMEM>>>(xhi, xlo, whi + 2 * (size_t)DM * DM,
                                     wlo + 2 * (size_t)DM * DM, v, S_TOTAL, DM, DM);

    attn_kernel<<<dim3(CHUNKL / 64, NHEAD, NCHUNK), 64>>>(q, k, v, a);

    split_hi_lo<<<(nx4 + 255) / 256, 256>>>(a, ahi, alo, nx4);
    gemm_mma<<<gg, 256, GEMM_SMEM>>>(ahi, alo, whi + 3 * (size_t)DM * DM,
                                     wlo + 3 * (size_t)DM * DM, out, S_TOTAL, DM, DM);
}

// round 13
// speedup vs baseline: 4.5948x; 2.0322x over previous
#include <cuda_runtime.h>
#include <cuda_bf16.h>
#include <math.h>
#include <stdint.h>

#define S_TOTAL 8192
#define DM      1024
#define NHEAD   16
#define HDIM    64
#define CHUNKL  2048
#define NCHUNK  4

// ---------------- scratch (allocation-free rule: __device__ globals) --------
__device__ __nv_bfloat16 g_xhi[S_TOTAL * DM];
__device__ __nv_bfloat16 g_xlo[S_TOTAL * DM];
__device__ __nv_bfloat16 g_qhi[S_TOTAL * DM];
__device__ __nv_bfloat16 g_qlo[S_TOTAL * DM];
__device__ __nv_bfloat16 g_khi[S_TOTAL * DM];
__device__ __nv_bfloat16 g_klo[S_TOTAL * DM];
__device__ __nv_bfloat16 g_vhi[S_TOTAL * DM];
__device__ __nv_bfloat16 g_vlo[S_TOTAL * DM];
__device__ __nv_bfloat16 g_ahi[S_TOTAL * DM];
__device__ __nv_bfloat16 g_alo[S_TOTAL * DM];
__device__ __nv_bfloat16 g_whi[4 * DM * DM];
__device__ __nv_bfloat16 g_wlo[4 * DM * DM];

// ---------------- warp-mma helpers (plain sm_103-safe PTX) ------------------
__device__ __forceinline__ uint32_t smem_u32(const void* p) {
    uint32_t a;
    asm("{ .reg .u64 t; cvta.to.shared.u64 t, %1; cvt.u32.u64 %0, t; }" : "=r"(a) : "l"(p));
    return a;
}
__device__ __forceinline__ void ldsm_x4(uint32_t* r, uint32_t addr) {
    asm volatile("ldmatrix.sync.aligned.m8n8.x4.shared.b16 {%0,%1,%2,%3}, [%4];"
                 : "=r"(r[0]), "=r"(r[1]), "=r"(r[2]), "=r"(r[3]) : "r"(addr));
}
__device__ __forceinline__ void ldsm_x4_t(uint32_t* r, uint32_t addr) {
    asm volatile("ldmatrix.sync.aligned.m8n8.x4.trans.shared.b16 {%0,%1,%2,%3}, [%4];"
                 : "=r"(r[0]), "=r"(r[1]), "=r"(r[2]), "=r"(r[3]) : "r"(addr));
}
__device__ __forceinline__ void mma_bf16(float* c, const uint32_t* a, const uint32_t* b) {
    asm volatile("mma.sync.aligned.m16n8k16.row.col.f32.bf16.bf16.f32 "
                 "{%0,%1,%2,%3}, {%4,%5,%6,%7}, {%8,%9}, {%0,%1,%2,%3};"
                 : "+f"(c[0]), "+f"(c[1]), "+f"(c[2]), "+f"(c[3])
                 : "r"(a[0]), "r"(a[1]), "r"(a[2]), "r"(a[3]), "r"(b[0]), "r"(b[1]));
}
__device__ __forceinline__ void cp_async16(uint32_t saddr, const void* gaddr) {
    asm volatile("cp.async.cg.shared.global [%0], [%1], 16;" :: "r"(saddr), "l"(gaddr));
}
__device__ __forceinline__ uint32_t pack_bf16(float lo, float hi) {
    __nv_bfloat162 t = __floats2bfloat162_rn(lo, hi);   // x=lo (low 16b), y=hi
    return *(uint32_t*)&t;
}

// ---------------- fp32 -> bf16 hi/lo split ----------------------------------
__global__ void __launch_bounds__(256) split_hi_lo(const float* __restrict__ src,
                                                   __nv_bfloat16* __restrict__ hi,
                                                   __nv_bfloat16* __restrict__ lo,
                                                   int n4) {
    int i = blockIdx.x * 256 + threadIdx.x;
    if (i >= n4) return;
    float4 v = ((const float4*)src)[i];
    float f[4] = {v.x, v.y, v.z, v.w};
    __align__(8) __nv_bfloat16 h[4], l[4];
#pragma unroll
    for (int j = 0; j < 4; j++) {
        h[j] = __float2bfloat16(f[j]);
        l[j] = __float2bfloat16(f[j] - __bfloat162float(h[j]));
    }
    ((uint2*)hi)[i] = *(uint2*)h;
    ((uint2*)lo)[i] = *(uint2*)l;
}

// ---------------- mma.sync GEMM, cp.async double-buffered -------------------
// C = AhiBhi + AhiBlo + AloBhi (fp32 accum). If Cf != null write fp32, else
// write bf16 hi/lo split to Chi/Clo.
#define BM 128
#define BN 64
#define BKC 32
#define STAGE_BYTES 30720
#define GEMM_SMEM   (2 * STAGE_BYTES)

__device__ __forceinline__ void gemm_prefetch(
    uint32_t stb, const __nv_bfloat16* const* aS, const __nv_bfloat16* const* bS,
    int bm, int bn, int kc, int K, int tid) {
#pragma unroll
    for (int s = 0; s < 2; s++) {
#pragma unroll
        for (int it = 0; it < 2; it++) {
            int id = tid + it * 256;
            int row = id >> 2, c16 = (id & 3) * 16;
            cp_async16(stb + s * 10240 + row * 80 + c16,
                       aS[s] + (size_t)(bm * BM + row) * K + kc + (c16 >> 1));
        }
        {
            int row = tid >> 2, c16 = (tid & 3) * 16;
            cp_async16(stb + 20480 + s * 5120 + row * 80 + c16,
                       bS[s] + (size_t)(bn * BN + row) * K + kc + (c16 >> 1));
        }
    }
}

__global__ void __launch_bounds__(256, 2) gemm_mma(
    const __nv_bfloat16* __restrict__ Ahi, const __nv_bfloat16* __restrict__ Alo,
    const __nv_bfloat16* __restrict__ Bhi, const __nv_bfloat16* __restrict__ Blo,
    float* __restrict__ Cf, __nv_bfloat16* __restrict__ Chi,
    __nv_bfloat16* __restrict__ Clo, int M, int N, int K) {
    extern __shared__ __align__(16) char smem[];
    const uint32_t sbase = smem_u32(smem);

    const int tid  = threadIdx.x;
    const int lane = tid & 31;
    const int warp = tid >> 5;
    const int wm = (warp & 1) * 64;
    const int wn = (warp >> 1) * 16;
    const int bm = blockIdx.x, bn = blockIdx.y;

    const uint32_t arow_off = (uint32_t)(wm + (lane & 15)) * 80 + (lane >> 4) * 16;
    const uint32_t bn_off =
        (uint32_t)(wn + (lane & 7) + ((lane >> 4) << 3)) * 80 + ((lane >> 3) & 1) * 16;

    const __nv_bfloat16* aS[2] = {Ahi, Alo};
    const __nv_bfloat16* bS[2] = {Bhi, Blo};

    float c[4][2][4];
#pragma unroll
    for (int i = 0; i < 4; i++)
#pragma unroll
        for (int j = 0; j < 2; j++)
#pragma unroll
            for (int t = 0; t < 4; t++) c[i][j][t] = 0.f;

    const int nk = K / BKC;

    gemm_prefetch(sbase, aS, bS, bm, bn, 0, K, tid);
    asm volatile("cp.async.commit_group;");

    for (int kc = 0; kc < nk; kc++) {
        const int st = kc & 1;
        if (kc + 1 < nk) {
            gemm_prefetch(sbase + (st ^ 1) * STAGE_BYTES, aS, bS, bm, bn,
                          (kc + 1) * BKC, K, tid);
            asm volatile("cp.async.commit_group;");
            asm volatile("cp.async.wait_group 1;");
        } else {
            asm volatile("cp.async.wait_group 0;");
        }
        __syncthreads();

        const uint32_t aHi = sbase + st * STAGE_BYTES + arow_off;
        const uint32_t bHi = sbase + st * STAGE_BYTES + 20480 + bn_off;

#pragma unroll
        for (int ks = 0; ks < 2; ks++) {
            uint32_t ah[4][4], al[4][4], bh[4], bl[4];
#pragma unroll
            for (int mt = 0; mt < 4; mt++)
                ldsm_x4(ah[mt], aHi + mt * (16 * 80) + ks * 32);
            ldsm_x4(bh, bHi + ks * 32);
#pragma unroll
            for (int mt = 0; mt < 4; mt++)
                ldsm_x4(al[mt], aHi + 10240 + mt * (16 * 80) + ks * 32);
            ldsm_x4(bl, bHi + 5120 + ks * 32);

#pragma unroll
            for (int mt = 0; mt < 4; mt++)
#pragma unroll
                for (int nt = 0; nt < 2; nt++) {
                    mma_bf16(c[mt][nt], ah[mt], &bh[nt * 2]);
                    mma_bf16(c[mt][nt], ah[mt], &bl[nt * 2]);
                    mma_bf16(c[mt][nt], al[mt], &bh[nt * 2]);
                }
        }
        __syncthreads();
    }

    const int r0 = bm * BM + wm + (lane >> 2);
    const int c0 = bn * BN + wn + (lane & 3) * 2;
#pragma unroll
    for (int mt = 0; mt < 4; mt++)
#pragma unroll
        for (int nt = 0; nt < 2; nt++) {
            const int row = r0 + mt * 16;
            const int col = c0 + nt * 8;
            if (Cf) {
                *(float2*)&Cf[(size_t)row * N + col]       = make_float2(c[mt][nt][0], c[mt][nt][1]);
                *(float2*)&Cf[(size_t)(row + 8) * N + col] = make_float2(c[mt][nt][2], c[mt][nt][3]);
            } else {
#pragma unroll
                for (int rr = 0; rr < 2; rr++) {
                    float v0 = c[mt][nt][rr * 2], v1 = c[mt][nt][rr * 2 + 1];
                    __nv_bfloat16 h0 = __float2bfloat16(v0);
                    __nv_bfloat16 h1 = __float2bfloat16(v1);
                    float l0 = v0 - __bfloat162float(h0);
                    float l1 = v1 - __bfloat162float(h1);
                    size_t off = (size_t)(row + rr * 8) * N + col;
                    __nv_bfloat162 hh; hh.x = h0; hh.y = h1;
                    *(uint32_t*)(Chi + off) = *(uint32_t*)&hh;
                    *(uint32_t*)(Clo + off) = pack_bf16(l0, l1);
                }
            }
        }
}

// ---------------- tensor-core chunk-local causal attention ------------------
// Block: 128 queries, 8 warps x 16 rows. 64-key tiles. hi/lo bf16 3-product
// for both QK^T and PV. grid (16 qb, 16 h, 4 ch), 256 threads.
#define ROWB 144
#define ATT_SMEM 36864

__global__ void __launch_bounds__(256) attn_mma(
    const __nv_bfloat16* __restrict__ qhi, const __nv_bfloat16* __restrict__ qlo,
    const __nv_bfloat16* __restrict__ khi, const __nv_bfloat16* __restrict__ klo,
    const __nv_bfloat16* __restrict__ vhi, const __nv_bfloat16* __restrict__ vlo,
    __nv_bfloat16* __restrict__ ohi, __nv_bfloat16* __restrict__ olo) {
    extern __shared__ __align__(16) char smem[];
    const uint32_t sb = smem_u32(smem);
    const int tid = threadIdx.x, lane = tid & 31, w = tid >> 5;
    const int qb = blockIdx.x, h = blockIdx.y, chk = blockIdx.z;
    const int chbase = chk * CHUNKL;

    // ---- stage Q tile (128 x 64 bf16, hi+lo) and extract A-frags ----
    {
        const __nv_bfloat16* qa[2] = {qhi, qlo};
#pragma unroll
        for (int i = 0; i < 8; i++) {
            int c = tid + i * 256;            // 0..2047
            int s = c >> 10;
            int row = (c >> 3) & 127;
            int chn = c & 7;
            uint4 vv = *(const uint4*)(qa[s] + (size_t)(chbase + qb * 128 + row) * DM
                                       + h * HDIM + chn * 8);
            *(uint4*)(smem + s * 18432 + row * ROWB + chn * 16) = vv;
        }
    }
    __syncthreads();
    uint32_t qh[4][4], ql[4][4];
    {
        uint32_t a_off = (uint32_t)(w * 16 + (lane & 15)) * ROWB + (lane >> 4) * 16;
#pragma unroll
        for (int ks = 0; ks < 4; ks++) {
            ldsm_x4(qh[ks], sb + a_off + ks * 32);
            ldsm_x4(ql[ks], sb + 18432 + a_off + ks * 32);
        }
    }
    __syncthreads();   // Q stage smem now reused for K/V

    float o[8][4];
#pragma unroll
    for (int i = 0; i < 8; i++)
#pragma unroll
        for (int j = 0; j < 4; j++) o[i][j] = 0.f;
    float m0 = -INFINITY, m1 = -INFINITY, l0 = 0.f, l1 = 0.f;

    const int qi0 = qb * 128 + w * 16 + (lane >> 2);
    const int ntiles = 2 * qb + 2;

    const uint32_t kb_off = (uint32_t)((lane & 7) + ((lane >> 4) << 3)) * ROWB
                            + ((lane >> 3) & 1) * 16;
    const uint32_t vb_off = (uint32_t)((lane & 7) + (((lane >> 3) & 1) << 3)) * ROWB
                            + (lane >> 4) * 16;

    const __nv_bfloat16* arrs[4] = {khi, klo, vhi, vlo};

    for (int kt = 0; kt < ntiles; kt++) {
        // ---- load K/V tile: 4 arrays x 64 rows x 128B ----
#pragma unroll
        for (int i = 0; i < 8; i++) {
            int c = tid + i * 256;            // 0..2047
            int s = c >> 9;
            int row = (c >> 3) & 63;
            int chn = c & 7;
            uint4 vv = *(const uint4*)(arrs[s] + (size_t)(chbase + kt * 64 + row) * DM
                                       + h * HDIM + chn * 8);
            *(uint4*)(smem + s * 9216 + row * ROWB + chn * 16) = vv;
        }
        __syncthreads();

        const bool skip = (kt * 64) > (qb * 128 + w * 16 + 15);
        if (!skip) {
            const bool need_mask = (kt * 64 + 63) > (qb * 128 + w * 16);

            // ---- S = Q K^T (3-product hi/lo) ----
            float s8[8][4];
#pragma unroll
            for (int i = 0; i < 8; i++)
#pragma unroll
                for (int j = 0; j < 4; j++) s8[i][j] = 0.f;
#pragma unroll
            for (int ks = 0; ks < 4; ks++) {
#pragma unroll
                for (int ng = 0; ng < 4; ng++) {
                    uint32_t bh[4], bl[4];
                    ldsm_x4(bh, sb + ng * (16 * ROWB) + kb_off + ks * 32);
                    ldsm_x4(bl, sb + 9216 + ng * (16 * ROWB) + kb_off + ks * 32);
                    mma_bf16(s8[2 * ng],     qh[ks], &bh[0]);
                    mma_bf16(s8[2 * ng],     qh[ks], &bl[0]);
                    mma_bf16(s8[2 * ng],     ql[ks], &bh[0]);
                    mma_bf16(s8[2 * ng + 1], qh[ks], &bh[2]);
                    mma_bf16(s8[2 * ng + 1], qh[ks], &bl[2]);
                    mma_bf16(s8[2 * ng + 1], ql[ks], &bh[2]);
                }
            }

            // ---- scale + causal mask ----
            float mt0 = -INFINITY, mt1 = -INFINITY;
#pragma unroll
            for (int nt = 0; nt < 8; nt++) {
                const int kcol = kt * 64 + nt * 8 + 2 * (lane & 3);
#pragma unroll
                for (int e = 0; e < 4; e++) s8[nt][e] *= 0.125f;
                if (need_mask) {
                    if (kcol     > qi0)     s8[nt][0] = -1e30f;
                    if (kcol + 1 > qi0)     s8[nt][1] = -1e30f;
                    if (kcol     > qi0 + 8) s8[nt][2] = -1e30f;
                    if (kcol + 1 > qi0 + 8) s8[nt][3] = -1e30f;
                }
                mt0 = fmaxf(mt0, fmaxf(s8[nt][0], s8[nt][1]));
                mt1 = fmaxf(mt1, fmaxf(s8[nt][2], s8[nt][3]));
            }
            mt0 = fmaxf(mt0, __shfl_xor_sync(0xffffffffu, mt0, 1));
            mt0 = fmaxf(mt0, __shfl_xor_sync(0xffffffffu, mt0, 2));
            mt1 = fmaxf(mt1, __shfl_xor_sync(0xffffffffu, mt1, 1));
            mt1 = fmaxf(mt1, __shfl_xor_sync(0xffffffffu, mt1, 2));

            const float mn0 = fmaxf(m0, mt0), mn1 = fmaxf(m1, mt1);
            const float cr0 = __expf(m0 - mn0), cr1 = __expf(m1 - mn1);
            m0 = mn0; m1 = mn1;
            l0 *= cr0; l1 *= cr1;
#pragma unroll
            for (int nt = 0; nt < 8; nt++) {
                o[nt][0] *= cr0; o[nt][1] *= cr0;
                o[nt][2] *= cr1; o[nt][3] *= cr1;
            }

            // ---- P = exp(S - m), accumulate l, build hi/lo A-frags ----
            uint32_t phh[8][2], pll[8][2];
#pragma unroll
            for (int nt = 0; nt < 8; nt++) {
                float p0 = __expf(s8[nt][0] - m0);
                float p1 = __expf(s8[nt][1] - m0);
                float p2 = __expf(s8[nt][2] - m1);
                float p3 = __expf(s8[nt][3] - m1);
                l0 += p0 + p1;
                l1 += p2 + p3;
                __nv_bfloat16 h0 = __float2bfloat16(p0), h1 = __float2bfloat16(p1);
                __nv_bfloat16 h2 = __float2bfloat16(p2), h3 = __float2bfloat16(p3);
                __nv_bfloat162 t01; t01.x = h0; t01.y = h1;
                __nv_bfloat162 t23; t23.x = h2; t23.y = h3;
                phh[nt][0] = *(uint32_t*)&t01;
                phh[nt][1] = *(uint32_t*)&t23;
                pll[nt][0] = pack_bf16(p0 - __bfloat162float(h0), p1 - __bfloat162float(h1));
                pll[nt][1] = pack_bf16(p2 - __bfloat162float(h2), p3 - __bfloat162float(h3));
            }

            // ---- O += P V (3-product hi/lo), V via ldmatrix.trans ----
#pragma unroll
            for (int s = 0; s < 4; s++) {
                uint32_t pa[4] = {phh[2 * s][0], phh[2 * s][1],
                                  phh[2 * s + 1][0], phh[2 * s + 1][1]};
                uint32_t pb[4] = {pll[2 * s][0], pll[2 * s][1],
                                  pll[2 * s + 1][0], pll[2 * s + 1][1]};
#pragma unroll
                for (int dg = 0; dg < 4; dg++) {
                    uint32_t bvh[4], bvl[4];
                    ldsm_x4_t(bvh, sb + 18432 + s * (16 * ROWB) + vb_off + dg * 32);
                    ldsm_x4_t(bvl, sb + 27648 + s * (16 * ROWB) + vb_off + dg * 32);
                    mma_bf16(o[2 * dg],     pa, &bvh[0]);
                    mma_bf16(o[2 * dg],     pa, &bvl[0]);
                    mma_bf16(o[2 * dg],     pb, &bvh[0]);
                    mma_bf16(o[2 * dg + 1], pa, &bvh[2]);
                    mma_bf16(o[2 * dg + 1], pa, &bvl[2]);
                    mma_bf16(o[2 * dg + 1], pb, &bvh[2]);
                }
            }
        }
        __syncthreads();
    }

    // ---- finalize: l quad-reduce, normalize, write bf16 hi/lo ----
    l0 += __shfl_xor_sync(0xffffffffu, l0, 1);
    l0 += __shfl_xor_sync(0xffffffffu, l0, 2);
    l1 += __shfl_xor_sync(0xffffffffu, l1, 1);
    l1 += __shfl_xor_sync(0xffffffffu, l1, 2);
    const float inv0 = 1.f / l0, inv1 = 1.f / l1;

    const size_t grow0 = (size_t)(chbase + qb * 128 + w * 16 + (lane >> 2)) * DM;
    const size_t grow1 = grow0 + 8 * DM;
#pragma unroll
    for (int nt = 0; nt < 8; nt++) {
        const int col = h * HDIM + nt * 8 + 2 * (lane & 3);
        float v0 = o[nt][0] * inv0, v1 = o[nt][1] * inv0;
        float v2 = o[nt][2] * inv1, v3 = o[nt][3] * inv1;
        __nv_bfloat16 h0 = __float2bfloat16(v0), h1 = __float2bfloat16(v1);
        __nv_bfloat16 h2 = __float2bfloat16(v2), h3 = __float2bfloat16(v3);
        __nv_bfloat162 t01; t01.x = h0; t01.y = h1;
        __nv_bfloat162 t23; t23.x = h2; t23.y = h3;
        *(uint32_t*)(ohi + grow0 + col) = *(uint32_t*)&t01;
        *(uint32_t*)(ohi + grow1 + col) = *(uint32_t*)&t23;
        *(uint32_t*)(olo + grow0 + col) = pack_bf16(v0 - __bfloat162float(h0),
                                                    v1 - __bfloat162float(h1));
        *(uint32_t*)(olo + grow1 + col) = pack_bf16(v2 - __bfloat162float(h2),
                                                    v3 - __bfloat162float(h3));
    }
}

// ---------------------------------------------------------------------------
extern "C" void kernel_launch(void* const* d_in, const int* in_sizes, int n_in,
                              void* d_out, int out_size) {
    const float* x  = (const float*)d_in[0];
    const float* Wq = (const float*)d_in[1];
    const float* Wk = (const float*)d_in[2];
    const float* Wv = (const float*)d_in[3];
    const float* Wo = (const float*)d_in[4];
    float* out = (float*)d_out;

    __nv_bfloat16 *xhi, *xlo, *qhi, *qlo, *khi, *klo, *vhi, *vlo, *ahi, *alo, *whi, *wlo;
    cudaGetSymbolAddress((void**)&xhi, g_xhi);
    cudaGetSymbolAddress((void**)&xlo, g_xlo);
    cudaGetSymbolAddress((void**)&qhi, g_qhi);
    cudaGetSymbolAddress((void**)&qlo, g_qlo);
    cudaGetSymbolAddress((void**)&khi, g_khi);
    cudaGetSymbolAddress((void**)&klo, g_klo);
    cudaGetSymbolAddress((void**)&vhi, g_vhi);
    cudaGetSymbolAddress((void**)&vlo, g_vlo);
    cudaGetSymbolAddress((void**)&ahi, g_ahi);
    cudaGetSymbolAddress((void**)&alo, g_alo);
    cudaGetSymbolAddress((void**)&whi, g_whi);
    cudaGetSymbolAddress((void**)&wlo, g_wlo);

    cudaFuncSetAttribute(gemm_mma, cudaFuncAttributeMaxDynamicSharedMemorySize, GEMM_SMEM);
    cudaFuncSetAttribute(attn_mma, cudaFuncAttributeMaxDynamicSharedMemorySize, ATT_SMEM);

    const int nx4 = S_TOTAL * DM / 4;
    const int nw4 = DM * DM / 4;
    const float* Ws[4] = {Wq, Wk, Wv, Wo};

    split_hi_lo<<<(nx4 + 255) / 256, 256>>>(x, xhi, xlo, nx4);
    for (int i = 0; i < 4; i++)
        split_hi_lo<<<(nw4 + 255) / 256, 256>>>(Ws[i], whi + (size_t)i * DM * DM,
                                                wlo + (size_t)i * DM * DM, nw4);

    dim3 gg(S_TOTAL / BM, DM / BN);   // (64, 16)
    gemm_mma<<<gg, 256, GEMM_SMEM>>>(xhi, xlo, whi + 0 * (size_t)DM * DM,
                                     wlo + 0 * (size_t)DM * DM, nullptr, qhi, qlo,
                                     S_TOTAL, DM, DM);
    gemm_mma<<<gg, 256, GEMM_SMEM>>>(xhi, xlo, whi + 1 * (size_t)DM * DM,
                                     wlo + 1 * (size_t)DM * DM, nullptr, khi, klo,
                                     S_TOTAL, DM, DM);
    gemm_mma<<<gg, 256, GEMM_SMEM>>>(xhi, xlo, whi + 2 * (size_t)DM * DM,
                                     wlo + 2 * (size_t)DM * DM, nullptr, vhi, vlo,
                                     S_TOTAL, DM, DM);

    attn_mma<<<dim3(CHUNKL / 128, NHEAD, NCHUNK), 256, ATT_SMEM>>>(
        qhi, qlo, khi, klo, vhi, vlo, ahi, alo);

    gemm_mma<<<gg, 256, GEMM_SMEM>>>(ahi, alo, whi + 3 * (size_t)DM * DM,
                                     wlo + 3 * (size_t)DM * DM, out, nullptr, nullptr,
                                     S_TOTAL, DM, DM);
}

// round 14
// speedup vs baseline: 4.8223x; 1.0495x over previous
#include <cuda_runtime.h>
#include <cuda_bf16.h>
#include <math.h>
#include <stdint.h>

#define S_TOTAL 8192
#define DM      1024
#define NHEAD   16
#define HDIM    64
#define CHUNKL  2048
#define NCHUNK  4

// ---------------- scratch (allocation-free rule: __device__ globals) --------
__device__ __nv_bfloat16 g_xhi[S_TOTAL * DM];
__device__ __nv_bfloat16 g_xlo[S_TOTAL * DM];
__device__ __nv_bfloat16 g_qhi[S_TOTAL * DM];
__device__ __nv_bfloat16 g_qlo[S_TOTAL * DM];
__device__ __nv_bfloat16 g_khi[S_TOTAL * DM];
__device__ __nv_bfloat16 g_klo[S_TOTAL * DM];
__device__ __nv_bfloat16 g_vhi[S_TOTAL * DM];
__device__ __nv_bfloat16 g_vlo[S_TOTAL * DM];
__device__ __nv_bfloat16 g_ahi[S_TOTAL * DM];
__device__ __nv_bfloat16 g_alo[S_TOTAL * DM];
__device__ __nv_bfloat16 g_whi[4 * DM * DM];
__device__ __nv_bfloat16 g_wlo[4 * DM * DM];

// ---------------- warp-mma helpers (plain sm_103-safe PTX) ------------------
__device__ __forceinline__ uint32_t smem_u32(const void* p) {
    uint32_t a;
    asm("{ .reg .u64 t; cvta.to.shared.u64 t, %1; cvt.u32.u64 %0, t; }" : "=r"(a) : "l"(p));
    return a;
}
__device__ __forceinline__ void ldsm_x4(uint32_t* r, uint32_t addr) {
    asm volatile("ldmatrix.sync.aligned.m8n8.x4.shared.b16 {%0,%1,%2,%3}, [%4];"
                 : "=r"(r[0]), "=r"(r[1]), "=r"(r[2]), "=r"(r[3]) : "r"(addr));
}
__device__ __forceinline__ void ldsm_x4_t(uint32_t* r, uint32_t addr) {
    asm volatile("ldmatrix.sync.aligned.m8n8.x4.trans.shared.b16 {%0,%1,%2,%3}, [%4];"
                 : "=r"(r[0]), "=r"(r[1]), "=r"(r[2]), "=r"(r[3]) : "r"(addr));
}
__device__ __forceinline__ void mma_bf16(float* c, const uint32_t* a, const uint32_t* b) {
    asm volatile("mma.sync.aligned.m16n8k16.row.col.f32.bf16.bf16.f32 "
                 "{%0,%1,%2,%3}, {%4,%5,%6,%7}, {%8,%9}, {%0,%1,%2,%3};"
                 : "+f"(c[0]), "+f"(c[1]), "+f"(c[2]), "+f"(c[3])
                 : "r"(a[0]), "r"(a[1]), "r"(a[2]), "r"(a[3]), "r"(b[0]), "r"(b[1]));
}
__device__ __forceinline__ void cp_async16(uint32_t saddr, const void* gaddr) {
    asm volatile("cp.async.cg.shared.global [%0], [%1], 16;" :: "r"(saddr), "l"(gaddr));
}
__device__ __forceinline__ uint32_t pack_bf16(float lo, float hi) {
    __nv_bfloat162 t = __floats2bfloat162_rn(lo, hi);
    return *(uint32_t*)&t;
}

// ---------------- fp32 -> bf16 hi/lo split ----------------------------------
__global__ void __launch_bounds__(256) split_hi_lo(const float* __restrict__ src,
                                                   __nv_bfloat16* __restrict__ hi,
                                                   __nv_bfloat16* __restrict__ lo,
                                                   int n4) {
    int i = blockIdx.x * 256 + threadIdx.x;
    if (i >= n4) return;
    float4 v = ((const float4*)src)[i];
    float f[4] = {v.x, v.y, v.z, v.w};
    __align__(8) __nv_bfloat16 h[4], l[4];
#pragma unroll
    for (int j = 0; j < 4; j++) {
        h[j] = __float2bfloat16(f[j]);
        l[j] = __float2bfloat16(f[j] - __bfloat162float(h[j]));
    }
    ((uint2*)hi)[i] = *(uint2*)h;
    ((uint2*)lo)[i] = *(uint2*)l;
}

// ---------------- mma.sync GEMM, cp.async double-buffered, 128x128 ----------
// C = AhiBhi + AhiBlo + AloBhi (fp32 accum). If Cf != null write fp32, else
// write bf16 hi/lo split to Chi/Clo.
#define BM 128
#define BN 128
#define BKC 32
// per-stage (bytes): Ahi@0 Alo@10240 Bhi@20480 Blo@30720  (each 128 rows x 80B)
#define STAGE_BYTES 40960
#define GEMM_SMEM   (2 * STAGE_BYTES)

__device__ __forceinline__ void gemm_prefetch(
    uint32_t stb, const __nv_bfloat16* const* aS, const __nv_bfloat16* const* bS,
    int bm, int bn, int kc, int K, int tid) {
#pragma unroll
    for (int s = 0; s < 2; s++) {
#pragma unroll
        for (int it = 0; it < 2; it++) {
            int id = tid + it * 256;                 // 0..511
            int row = id >> 2, c16 = (id & 3) * 16;  // 128 rows x 4 x 16B
            cp_async16(stb + s * 10240 + row * 80 + c16,
                       aS[s] + (size_t)(bm * BM + row) * K + kc + (c16 >> 1));
        }
#pragma unroll
        for (int it = 0; it < 2; it++) {
            int id = tid + it * 256;
            int row = id >> 2, c16 = (id & 3) * 16;
            cp_async16(stb + 20480 + s * 10240 + row * 80 + c16,
                       bS[s] + (size_t)(bn * BN + row) * K + kc + (c16 >> 1));
        }
    }
}

__global__ void __launch_bounds__(256, 2) gemm_mma(
    const __nv_bfloat16* __restrict__ Ahi, const __nv_bfloat16* __restrict__ Alo,
    const __nv_bfloat16* __restrict__ Bhi, const __nv_bfloat16* __restrict__ Blo,
    float* __restrict__ Cf, __nv_bfloat16* __restrict__ Chi,
    __nv_bfloat16* __restrict__ Clo, int M, int N, int K) {
    extern __shared__ __align__(16) char smem[];
    const uint32_t sbase = smem_u32(smem);

    const int tid  = threadIdx.x;
    const int lane = tid & 31;
    const int warp = tid >> 5;
    const int wm = (warp & 1) * 64;     // warp M offset (2 warps in M)
    const int wn = (warp >> 1) * 32;    // warp N offset (4 warps in N)
    const int bm = blockIdx.x, bn = blockIdx.y;

    const uint32_t arow_off = (uint32_t)(wm + (lane & 15)) * 80 + (lane >> 4) * 16;
    const uint32_t bn_off =
        (uint32_t)(wn + (lane & 7) + ((lane >> 4) << 3)) * 80 + ((lane >> 3) & 1) * 16;

    const __nv_bfloat16* aS[2] = {Ahi, Alo};
    const __nv_bfloat16* bS[2] = {Bhi, Blo};

    float c[4][4][4];
#pragma unroll
    for (int i = 0; i < 4; i++)
#pragma unroll
        for (int j = 0; j < 4; j++)
#pragma unroll
            for (int t = 0; t < 4; t++) c[i][j][t] = 0.f;

    const int nk = K / BKC;

    gemm_prefetch(sbase, aS, bS, bm, bn, 0, K, tid);
    asm volatile("cp.async.commit_group;");

    for (int kc = 0; kc < nk; kc++) {
        const int st = kc & 1;
        if (kc + 1 < nk) {
            gemm_prefetch(sbase + (st ^ 1) * STAGE_BYTES, aS, bS, bm, bn,
                          (kc + 1) * BKC, K, tid);
            asm volatile("cp.async.commit_group;");
            asm volatile("cp.async.wait_group 1;");
        } else {
            asm volatile("cp.async.wait_group 0;");
        }
        __syncthreads();

        const uint32_t aHi = sbase + st * STAGE_BYTES + arow_off;
        const uint32_t bBs = sbase + st * STAGE_BYTES + 20480 + bn_off;

#pragma unroll
        for (int ks = 0; ks < 2; ks++) {
            uint32_t bh[8], bl[8];
            ldsm_x4(bh,     bBs + ks * 32);
            ldsm_x4(bh + 4, bBs + 16 * 80 + ks * 32);
            ldsm_x4(bl,     bBs + 10240 + ks * 32);
            ldsm_x4(bl + 4, bBs + 10240 + 16 * 80 + ks * 32);

#pragma unroll
            for (int mt = 0; mt < 4; mt++) {
                uint32_t ah[4], al[4];
                ldsm_x4(ah, aHi + mt * (16 * 80) + ks * 32);
                ldsm_x4(al, aHi + 10240 + mt * (16 * 80) + ks * 32);
#pragma unroll
                for (int nt = 0; nt < 4; nt++) {
                    mma_bf16(c[mt][nt], ah, &bh[nt * 2]);   // hi*hi
                    mma_bf16(c[mt][nt], ah, &bl[nt * 2]);   // hi*lo
                    mma_bf16(c[mt][nt], al, &bh[nt * 2]);   // lo*hi
                }
            }
        }
        __syncthreads();
    }

    const int r0 = bm * BM + wm + (lane >> 2);
    const int c0 = bn * BN + wn + (lane & 3) * 2;
#pragma unroll
    for (int mt = 0; mt < 4; mt++)
#pragma unroll
        for (int nt = 0; nt < 4; nt++) {
            const int row = r0 + mt * 16;
            const int col = c0 + nt * 8;
            if (Cf) {
                *(float2*)&Cf[(size_t)row * N + col]       = make_float2(c[mt][nt][0], c[mt][nt][1]);
                *(float2*)&Cf[(size_t)(row + 8) * N + col] = make_float2(c[mt][nt][2], c[mt][nt][3]);
            } else {
#pragma unroll
                for (int rr = 0; rr < 2; rr++) {
                    float v0 = c[mt][nt][rr * 2], v1 = c[mt][nt][rr * 2 + 1];
                    __nv_bfloat16 h0 = __float2bfloat16(v0);
                    __nv_bfloat16 h1 = __float2bfloat16(v1);
                    float l0 = v0 - __bfloat162float(h0);
                    float l1 = v1 - __bfloat162float(h1);
                    size_t off = (size_t)(row + rr * 8) * N + col;
                    __nv_bfloat162 hh; hh.x = h0; hh.y = h1;
                    *(uint32_t*)(Chi + off) = *(uint32_t*)&hh;
                    *(uint32_t*)(Clo + off) = pack_bf16(l0, l1);
                }
            }
        }
}

// ---------------- tensor-core chunk-local causal attention (R13) ------------
#define ROWB 144
#define ATT_SMEM 36864

__global__ void __launch_bounds__(256) attn_mma(
    const __nv_bfloat16* __restrict__ qhi, const __nv_bfloat16* __restrict__ qlo,
    const __nv_bfloat16* __restrict__ khi, const __nv_bfloat16* __restrict__ klo,
    const __nv_bfloat16* __restrict__ vhi, const __nv_bfloat16* __restrict__ vlo,
    __nv_bfloat16* __restrict__ ohi, __nv_bfloat16* __restrict__ olo) {
    extern __shared__ __align__(16) char smem[];
    const uint32_t sb = smem_u32(smem);
    const int tid = threadIdx.x, lane = tid & 31, w = tid >> 5;
    const int qb = blockIdx.x, h = blockIdx.y, chk = blockIdx.z;
    const int chbase = chk * CHUNKL;

    {
        const __nv_bfloat16* qa[2] = {qhi, qlo};
#pragma unroll
        for (int i = 0; i < 8; i++) {
            int c = tid + i * 256;
            int s = c >> 10;
            int row = (c >> 3) & 127;
            int chn = c & 7;
            uint4 vv = *(const uint4*)(qa[s] + (size_t)(chbase + qb * 128 + row) * DM
                                       + h * HDIM + chn * 8);
            *(uint4*)(smem + s * 18432 + row * ROWB + chn * 16) = vv;
        }
    }
    __syncthreads();
    uint32_t qh[4][4], ql[4][4];
    {
        uint32_t a_off = (uint32_t)(w * 16 + (lane & 15)) * ROWB + (lane >> 4) * 16;
#pragma unroll
        for (int ks = 0; ks < 4; ks++) {
            ldsm_x4(qh[ks], sb + a_off + ks * 32);
            ldsm_x4(ql[ks], sb + 18432 + a_off + ks * 32);
        }
    }
    __syncthreads();

    float o[8][4];
#pragma unroll
    for (int i = 0; i < 8; i++)
#pragma unroll
        for (int j = 0; j < 4; j++) o[i][j] = 0.f;
    float m0 = -INFINITY, m1 = -INFINITY, l0 = 0.f, l1 = 0.f;

    const int qi0 = qb * 128 + w * 16 + (lane >> 2);
    const int ntiles = 2 * qb + 2;

    const uint32_t kb_off = (uint32_t)((lane & 7) + ((lane >> 4) << 3)) * ROWB
                            + ((lane >> 3) & 1) * 16;
    const uint32_t vb_off = (uint32_t)((lane & 7) + (((lane >> 3) & 1) << 3)) * ROWB
                            + (lane >> 4) * 16;

    const __nv_bfloat16* arrs[4] = {khi, klo, vhi, vlo};

    for (int kt = 0; kt < ntiles; kt++) {
#pragma unroll
        for (int i = 0; i < 8; i++) {
            int c = tid + i * 256;
            int s = c >> 9;
            int row = (c >> 3) & 63;
            int chn = c & 7;
            uint4 vv = *(const uint4*)(arrs[s] + (size_t)(chbase + kt * 64 + row) * DM
                                       + h * HDIM + chn * 8);
            *(uint4*)(smem + s * 9216 + row * ROWB + chn * 16) = vv;
        }
        __syncthreads();

        const bool skip = (kt * 64) > (qb * 128 + w * 16 + 15);
        if (!skip) {
            const bool need_mask = (kt * 64 + 63) > (qb * 128 + w * 16);

            float s8[8][4];
#pragma unroll
            for (int i = 0; i < 8; i++)
#pragma unroll
                for (int j = 0; j < 4; j++) s8[i][j] = 0.f;
#pragma unroll
            for (int ks = 0; ks < 4; ks++) {
#pragma unroll
                for (int ng = 0; ng < 4; ng++) {
                    uint32_t bh[4], bl[4];
                    ldsm_x4(bh, sb + ng * (16 * ROWB) + kb_off + ks * 32);
                    ldsm_x4(bl, sb + 9216 + ng * (16 * ROWB) + kb_off + ks * 32);
                    mma_bf16(s8[2 * ng],     qh[ks], &bh[0]);
                    mma_bf16(s8[2 * ng],     qh[ks], &bl[0]);
                    mma_bf16(s8[2 * ng],     ql[ks], &bh[0]);
                    mma_bf16(s8[2 * ng + 1], qh[ks], &bh[2]);
                    mma_bf16(s8[2 * ng + 1], qh[ks], &bl[2]);
                    mma_bf16(s8[2 * ng + 1], ql[ks], &bh[2]);
                }
            }

            float mt0 = -INFINITY, mt1 = -INFINITY;
#pragma unroll
            for (int nt = 0; nt < 8; nt++) {
                const int kcol = kt * 64 + nt * 8 + 2 * (lane & 3);
#pragma unroll
                for (int e = 0; e < 4; e++) s8[nt][e] *= 0.125f;
                if (need_mask) {
                    if (kcol     > qi0)     s8[nt][0] = -1e30f;
                    if (kcol + 1 > qi0)     s8[nt][1] = -1e30f;
                    if (kcol     > qi0 + 8) s8[nt][2] = -1e30f;
                    if (kcol + 1 > qi0 + 8) s8[nt][3] = -1e30f;
                }
                mt0 = fmaxf(mt0, fmaxf(s8[nt][0], s8[nt][1]));
                mt1 = fmaxf(mt1, fmaxf(s8[nt][2], s8[nt][3]));
            }
            mt0 = fmaxf(mt0, __shfl_xor_sync(0xffffffffu, mt0, 1));
            mt0 = fmaxf(mt0, __shfl_xor_sync(0xffffffffu, mt0, 2));
            mt1 = fmaxf(mt1, __shfl_xor_sync(0xffffffffu, mt1, 1));
            mt1 = fmaxf(mt1, __shfl_xor_sync(0xffffffffu, mt1, 2));

            const float mn0 = fmaxf(m0, mt0), mn1 = fmaxf(m1, mt1);
            const float cr0 = __expf(m0 - mn0), cr1 = __expf(m1 - mn1);
            m0 = mn0; m1 = mn1;
            l0 *= cr0; l1 *= cr1;
#pragma unroll
            for (int nt = 0; nt < 8; nt++) {
                o[nt][0] *= cr0; o[nt][1] *= cr0;
                o[nt][2] *= cr1; o[nt][3] *= cr1;
            }

            uint32_t phh[8][2], pll[8][2];
#pragma unroll
            for (int nt = 0; nt < 8; nt++) {
                float p0 = __expf(s8[nt][0] - m0);
                float p1 = __expf(s8[nt][1] - m0);
                float p2 = __expf(s8[nt][2] - m1);
                float p3 = __expf(s8[nt][3] - m1);
                l0 += p0 + p1;
                l1 += p2 + p3;
                __nv_bfloat16 h0 = __float2bfloat16(p0), h1 = __float2bfloat16(p1);
                __nv_bfloat16 h2 = __float2bfloat16(p2), h3 = __float2bfloat16(p3);
                __nv_bfloat162 t01; t01.x = h0; t01.y = h1;
                __nv_bfloat162 t23; t23.x = h2; t23.y = h3;
                phh[nt][0] = *(uint32_t*)&t01;
                phh[nt][1] = *(uint32_t*)&t23;
                pll[nt][0] = pack_bf16(p0 - __bfloat162float(h0), p1 - __bfloat162float(h1));
                pll[nt][1] = pack_bf16(p2 - __bfloat162float(h2), p3 - __bfloat162float(h3));
            }

#pragma unroll
            for (int s = 0; s < 4; s++) {
                uint32_t pa[4] = {phh[2 * s][0], phh[2 * s][1],
                                  phh[2 * s + 1][0], phh[2 * s + 1][1]};
                uint32_t pb[4] = {pll[2 * s][0], pll[2 * s][1],
                                  pll[2 * s + 1][0], pll[2 * s + 1][1]};
#pragma unroll
                for (int dg = 0; dg < 4; dg++) {
                    uint32_t bvh[4], bvl[4];
                    ldsm_x4_t(bvh, sb + 18432 + s * (16 * ROWB) + vb_off + dg * 32);
                    ldsm_x4_t(bvl, sb + 27648 + s * (16 * ROWB) + vb_off + dg * 32);
                    mma_bf16(o[2 * dg],     pa, &bvh[0]);
                    mma_bf16(o[2 * dg],     pa, &bvl[0]);
                    mma_bf16(o[2 * dg],     pb, &bvh[0]);
                    mma_bf16(o[2 * dg + 1], pa, &bvh[2]);
                    mma_bf16(o[2 * dg + 1], pa, &bvl[2]);
                    mma_bf16(o[2 * dg + 1], pb, &bvh[2]);
                }
            }
        }
        __syncthreads();
    }

    l0 += __shfl_xor_sync(0xffffffffu, l0, 1);
    l0 += __shfl_xor_sync(0xffffffffu, l0, 2);
    l1 += __shfl_xor_sync(0xffffffffu, l1, 1);
    l1 += __shfl_xor_sync(0xffffffffu, l1, 2);
    const float inv0 = 1.f / l0, inv1 = 1.f / l1;

    const size_t grow0 = (size_t)(chbase + qb * 128 + w * 16 + (lane >> 2)) * DM;
    const size_t grow1 = grow0 + 8 * DM;
#pragma unroll
    for (int nt = 0; nt < 8; nt++) {
        const int col = h * HDIM + nt * 8 + 2 * (lane & 3);
        float v0 = o[nt][0] * inv0, v1 = o[nt][1] * inv0;
        float v2 = o[nt][2] * inv1, v3 = o[nt][3] * inv1;
        __nv_bfloat16 h0 = __float2bfloat16(v0), h1 = __float2bfloat16(v1);
        __nv_bfloat16 h2 = __float2bfloat16(v2), h3 = __float2bfloat16(v3);
        __nv_bfloat162 t01; t01.x = h0; t01.y = h1;
        __nv_bfloat162 t23; t23.x = h2; t23.y = h3;
        *(uint32_t*)(ohi + grow0 + col) = *(uint32_t*)&t01;
        *(uint32_t*)(ohi + grow1 + col) = *(uint32_t*)&t23;
        *(uint32_t*)(olo + grow0 + col) = pack_bf16(v0 - __bfloat162float(h0),
                                                    v1 - __bfloat162float(h1));
        *(uint32_t*)(olo + grow1 + col) = pack_bf16(v2 - __bfloat162float(h2),
                                                    v3 - __bfloat162float(h3));
    }
}

// ---------------------------------------------------------------------------
extern "C" void kernel_launch(void* const* d_in, const int* in_sizes, int n_in,
                              void* d_out, int out_size) {
    const float* x  = (const float*)d_in[0];
    const float* Wq = (const float*)d_in[1];
    const float* Wk = (const float*)d_in[2];
    const float* Wv = (const float*)d_in[3];
    const float* Wo = (const float*)d_in[4];
    float* out = (float*)d_out;

    __nv_bfloat16 *xhi, *xlo, *qhi, *qlo, *khi, *klo, *vhi, *vlo, *ahi, *alo, *whi, *wlo;
    cudaGetSymbolAddress((void**)&xhi, g_xhi);
    cudaGetSymbolAddress((void**)&xlo, g_xlo);
    cudaGetSymbolAddress((void**)&qhi, g_qhi);
    cudaGetSymbolAddress((void**)&qlo, g_qlo);
    cudaGetSymbolAddress((void**)&khi, g_khi);
    cudaGetSymbolAddress((void**)&klo, g_klo);
    cudaGetSymbolAddress((void**)&vhi, g_vhi);
    cudaGetSymbolAddress((void**)&vlo, g_vlo);
    cudaGetSymbolAddress((void**)&ahi, g_ahi);
    cudaGetSymbolAddress((void**)&alo, g_alo);
    cudaGetSymbolAddress((void**)&whi, g_whi);
    cudaGetSymbolAddress((void**)&wlo, g_wlo);

    cudaFuncSetAttribute(gemm_mma, cudaFuncAttributeMaxDynamicSharedMemorySize, GEMM_SMEM);
    cudaFuncSetAttribute(attn_mma, cudaFuncAttributeMaxDynamicSharedMemorySize, ATT_SMEM);

    const int nx4 = S_TOTAL * DM / 4;
    const int nw4 = DM * DM / 4;
    const float* Ws[4] = {Wq, Wk, Wv, Wo};

    split_hi_lo<<<(nx4 + 255) / 256, 256>>>(x, xhi, xlo, nx4);
    for (int i = 0; i < 4; i++)
        split_hi_lo<<<(nw4 + 255) / 256, 256>>>(Ws[i], whi + (size_t)i * DM * DM,
                                                wlo + (size_t)i * DM * DM, nw4);

    dim3 gg(S_TOTAL / BM, DM / BN);   // (64, 8)
    gemm_mma<<<gg, 256, GEMM_SMEM>>>(xhi, xlo, whi + 0 * (size_t)DM * DM,
                                     wlo + 0 * (size_t)DM * DM, nullptr, qhi, qlo,
                                     S_TOTAL, DM, DM);
    gemm_mma<<<gg, 256, GEMM_SMEM>>>(xhi, xlo, whi + 1 * (size_t)DM * DM,
                                     wlo + 1 * (size_t)DM * DM, nullptr, khi, klo,
                                     S_TOTAL, DM, DM);
    gemm_mma<<<gg, 256, GEMM_SMEM>>>(xhi, xlo, whi + 2 * (size_t)DM * DM,
                                     wlo + 2 * (size_t)DM * DM, nullptr, vhi, vlo,
                                     S_TOTAL, DM, DM);

    attn_mma<<<dim3(CHUNKL / 128, NHEAD, NCHUNK), 256, ATT_SMEM>>>(
        qhi, qlo, khi, klo, vhi, vlo, ahi, alo);

    gemm_mma<<<gg, 256, GEMM_SMEM>>>(ahi, alo, whi + 3 * (size_t)DM * DM,
                                     wlo + 3 * (size_t)DM * DM, out, nullptr, nullptr,
                                     S_TOTAL, DM, DM);
}